// round 1
// baseline (speedup 1.0000x reference)
#include <cuda_runtime.h>

// BayesianMetaPosterior: scalar loss from two reductions.
//   S_sq  = sum(metamean^2)            over D elements
//   S_log = sum(log(fishers))          over M*D elements
//   loss  = (M-1) * ( S_sq/(2*sigma^2) + D*(log(sigma) + 0.5*log(2pi)) )
//         + ( -0.5*M*D*log(2pi) + 0.5*S_log )
// `means` input is mathematically unused (Mahalanobis term is identically 0).

#define NBLOCKS  2048
#define NTHREADS 256

__device__ double g_part_sq[NBLOCKS];
__device__ double g_part_log[NBLOCKS];

__global__ __launch_bounds__(NTHREADS)
void bmp_reduce_kernel(const float* __restrict__ metamean,
                       const float* __restrict__ fishers,
                       long long D, long long MD)
{
    const long long tid    = (long long)blockIdx.x * blockDim.x + threadIdx.x;
    const long long stride = (long long)gridDim.x * blockDim.x;

    double acc_sq = 0.0, acc_log = 0.0;

    // ---- sum of squares over metamean (vectorized float4) ----
    {
        const long long n4 = D >> 2;
        const float4* mm4 = reinterpret_cast<const float4*>(metamean);
        float fs = 0.0f;
        int cnt = 0;
        for (long long i = tid; i < n4; i += stride) {
            float4 v = __ldg(&mm4[i]);
            fs += v.x * v.x + v.y * v.y + v.z * v.z + v.w * v.w;
            if (++cnt == 32) { acc_sq += (double)fs; fs = 0.0f; cnt = 0; }
        }
        acc_sq += (double)fs;
        for (long long i = (n4 << 2) + tid; i < D; i += stride) {
            float v = __ldg(&metamean[i]);
            acc_sq += (double)(v * v);
        }
    }

    // ---- sum of logs over fishers (vectorized float4, fast MUFU log) ----
    {
        const long long m4 = MD >> 2;
        const float4* f4 = reinterpret_cast<const float4*>(fishers);
        float fs = 0.0f;
        int cnt = 0;
        for (long long i = tid; i < m4; i += stride) {
            float4 v = __ldg(&f4[i]);
            fs += __logf(v.x) + __logf(v.y) + __logf(v.z) + __logf(v.w);
            if (++cnt == 32) { acc_log += (double)fs; fs = 0.0f; cnt = 0; }
        }
        acc_log += (double)fs;
        for (long long i = (m4 << 2) + tid; i < MD; i += stride) {
            acc_log += (double)__logf(__ldg(&fishers[i]));
        }
    }

    // ---- deterministic block tree-reduce in shared memory ----
    __shared__ double s_sq[NTHREADS];
    __shared__ double s_lg[NTHREADS];
    s_sq[threadIdx.x] = acc_sq;
    s_lg[threadIdx.x] = acc_log;
    __syncthreads();
    #pragma unroll
    for (int off = NTHREADS / 2; off > 0; off >>= 1) {
        if ((int)threadIdx.x < off) {
            s_sq[threadIdx.x] += s_sq[threadIdx.x + off];
            s_lg[threadIdx.x] += s_lg[threadIdx.x + off];
        }
        __syncthreads();
    }
    if (threadIdx.x == 0) {
        g_part_sq[blockIdx.x]  = s_sq[0];
        g_part_log[blockIdx.x] = s_lg[0];
    }
}

__global__ __launch_bounds__(1024)
void bmp_final_kernel(float* __restrict__ out, int out_size,
                      long long D, int M)
{
    __shared__ double s_sq[1024];
    __shared__ double s_lg[1024];
    double a = 0.0, b = 0.0;
    for (int i = threadIdx.x; i < NBLOCKS; i += blockDim.x) {
        a += g_part_sq[i];
        b += g_part_log[i];
    }
    s_sq[threadIdx.x] = a;
    s_lg[threadIdx.x] = b;
    __syncthreads();
    for (int off = 512; off > 0; off >>= 1) {
        if ((int)threadIdx.x < off) {
            s_sq[threadIdx.x] += s_sq[threadIdx.x + off];
            s_lg[threadIdx.x] += s_lg[threadIdx.x + off];
        }
        __syncthreads();
    }
    if (threadIdx.x == 0) {
        const double log2pi  = 1.8378770664093453;      // log(2*pi)
        const double logsig  = -2.3025850929940456840;  // log(0.1)
        const double inv2s2  = 50.0;                    // 1/(2*0.1^2)
        const double S_sq  = s_sq[0];
        const double S_log = s_lg[0];

        double prior_term = (double)(M - 1) *
            (inv2s2 * S_sq + (double)D * (logsig + 0.5 * log2pi));
        double post_term  = -0.5 * (double)M * (double)D * log2pi + 0.5 * S_log;
        float loss = (float)(prior_term + post_term);
        for (int i = 0; i < out_size; i++) out[i] = loss;
    }
}

extern "C" void kernel_launch(void* const* d_in, const int* in_sizes, int n_in,
                              void* d_out, int out_size)
{
    const float* metamean = (const float*)d_in[0];
    // d_in[1] = means: unused (Mahalanobis term is identically zero)
    const float* fishers  = (const float*)d_in[2];

    const long long D  = (long long)in_sizes[0];
    const long long MD = (long long)in_sizes[2];
    const int M = (int)(MD / D);

    bmp_reduce_kernel<<<NBLOCKS, NTHREADS>>>(metamean, fishers, D, MD);
    bmp_final_kernel<<<1, 1024>>>((float*)d_out, out_size, D, M);
}

// round 2
// speedup vs baseline: 1.7689x; 1.7689x over previous
#include <cuda_runtime.h>

// BayesianMetaPosterior: scalar loss from two reductions.
//   S_sq  = sum(metamean^2)   over D elements
//   S_log = sum(log(fishers)) over M*D elements
//   loss  = (M-1)*( S_sq/(2*sigma^2) + D*(log(sigma)+0.5*log(2pi)) )
//         + ( -0.5*M*D*log(2pi) + 0.5*S_log )
// `means` (d_in[1]) is mathematically unused (Mahalanobis term == 0).
//
// Single fused kernel: grid split 1:3 (metamean:fishers), unroll-4 float4
// streaming loads for MLP, float accumulators in the hot loop, double only
// at block-reduce. Last-finished block performs the final reduction.

#define NB_M 296
#define NB_F 888
#define NB   (NB_M + NB_F)   // 1184 = 148 SMs * 8 CTAs (one wave @ 256 thr)
#define NT   256

__device__ double g_part_sq[NB_M];
__device__ double g_part_log[NB_F];
__device__ unsigned int g_done_count;   // zero-init; self-resets each run

__device__ __forceinline__ double block_reduce(double v) {
    __shared__ double sm[NT / 32];
    // warp reduce
    #pragma unroll
    for (int off = 16; off > 0; off >>= 1)
        v += __shfl_down_sync(0xFFFFFFFFu, v, off);
    int lane = threadIdx.x & 31, warp = threadIdx.x >> 5;
    if (lane == 0) sm[warp] = v;
    __syncthreads();
    if (warp == 0) {
        v = (lane < NT / 32) ? sm[lane] : 0.0;
        #pragma unroll
        for (int off = 4; off > 0; off >>= 1)
            v += __shfl_down_sync(0xFFFFFFFFu, v, off);
    }
    return v;  // valid in thread 0
}

__global__ __launch_bounds__(NT)
void bmp_kernel(const float* __restrict__ metamean,
                const float* __restrict__ fishers,
                long long D, long long MD, int M,
                float* __restrict__ out, int out_size)
{
    const bool is_fish = (blockIdx.x >= NB_M);
    const float4* __restrict__ src =
        reinterpret_cast<const float4*>(is_fish ? fishers : metamean);
    const long long nElem = is_fish ? MD : D;
    const long long n4    = nElem >> 2;
    const int  bid = is_fish ? (int)blockIdx.x - NB_M : (int)blockIdx.x;
    const int  nb  = is_fish ? NB_F : NB_M;
    const long long tid    = (long long)bid * NT + threadIdx.x;
    const long long stride = (long long)nb * NT;

    float a0 = 0.f, a1 = 0.f, a2 = 0.f, a3 = 0.f;
    long long i = tid;

    if (is_fish) {
        // ---- sum of __logf over fishers ----
        for (; i + 3 * stride < n4; i += 4 * stride) {
            float4 v0 = __ldcs(&src[i]);
            float4 v1 = __ldcs(&src[i + stride]);
            float4 v2 = __ldcs(&src[i + 2 * stride]);
            float4 v3 = __ldcs(&src[i + 3 * stride]);
            a0 += __logf(v0.x) + __logf(v0.y) + __logf(v0.z) + __logf(v0.w);
            a1 += __logf(v1.x) + __logf(v1.y) + __logf(v1.z) + __logf(v1.w);
            a2 += __logf(v2.x) + __logf(v2.y) + __logf(v2.z) + __logf(v2.w);
            a3 += __logf(v3.x) + __logf(v3.y) + __logf(v3.z) + __logf(v3.w);
        }
        for (; i < n4; i += stride) {
            float4 v = __ldcs(&src[i]);
            a0 += __logf(v.x) + __logf(v.y) + __logf(v.z) + __logf(v.w);
        }
        for (long long j = (n4 << 2) + tid; j < nElem; j += stride)
            a0 += __logf(__ldg(&fishers[j]));
    } else {
        // ---- sum of squares over metamean ----
        for (; i + 3 * stride < n4; i += 4 * stride) {
            float4 v0 = __ldcs(&src[i]);
            float4 v1 = __ldcs(&src[i + stride]);
            float4 v2 = __ldcs(&src[i + 2 * stride]);
            float4 v3 = __ldcs(&src[i + 3 * stride]);
            a0 += v0.x * v0.x + v0.y * v0.y + v0.z * v0.z + v0.w * v0.w;
            a1 += v1.x * v1.x + v1.y * v1.y + v1.z * v1.z + v1.w * v1.w;
            a2 += v2.x * v2.x + v2.y * v2.y + v2.z * v2.z + v2.w * v2.w;
            a3 += v3.x * v3.x + v3.y * v3.y + v3.z * v3.z + v3.w * v3.w;
        }
        for (; i < n4; i += stride) {
            float4 v = __ldcs(&src[i]);
            a0 += v.x * v.x + v.y * v.y + v.z * v.z + v.w * v.w;
        }
        for (long long j = (n4 << 2) + tid; j < nElem; j += stride) {
            float v = __ldg(&metamean[j]);
            a0 += v * v;
        }
    }

    double acc = ((double)a0 + (double)a1) + ((double)a2 + (double)a3);
    acc = block_reduce(acc);

    __shared__ bool s_last;
    if (threadIdx.x == 0) {
        if (is_fish) g_part_log[bid] = acc;
        else         g_part_sq[bid]  = acc;
        __threadfence();
        unsigned int prev = atomicAdd(&g_done_count, 1u);
        s_last = (prev == NB - 1);
    }
    __syncthreads();

    // ---- last block to finish performs the final reduction ----
    if (s_last) {
        double a = 0.0, b = 0.0;
        for (int k = threadIdx.x; k < NB_M; k += NT) a += g_part_sq[k];
        for (int k = threadIdx.x; k < NB_F; k += NT) b += g_part_log[k];
        a = block_reduce(a);
        __syncthreads();           // reuse of block_reduce smem
        b = block_reduce(b);
        if (threadIdx.x == 0) {
            const double log2pi = 1.8378770664093453;      // log(2*pi)
            const double logsig = -2.3025850929940456840;  // log(0.1)
            const double inv2s2 = 50.0;                    // 1/(2*0.1^2)
            double prior_term = (double)(M - 1) *
                (inv2s2 * a + (double)D * (logsig + 0.5 * log2pi));
            double post_term = -0.5 * (double)M * (double)D * log2pi + 0.5 * b;
            float loss = (float)(prior_term + post_term);
            for (int k = 0; k < out_size; k++) out[k] = loss;
            g_done_count = 0;      // self-reset for next graph replay
        }
    }
}

extern "C" void kernel_launch(void* const* d_in, const int* in_sizes, int n_in,
                              void* d_out, int out_size)
{
    const float* metamean = (const float*)d_in[0];
    // d_in[1] = means: unused (Mahalanobis term is identically zero)
    const float* fishers  = (const float*)d_in[2];

    const long long D  = (long long)in_sizes[0];
    const long long MD = (long long)in_sizes[2];
    const int M = (int)(MD / D);

    bmp_kernel<<<NB, NT>>>(metamean, fishers, D, MD, M,
                           (float*)d_out, out_size);
}

// round 3
// speedup vs baseline: 1.8635x; 1.0535x over previous
#include <cuda_runtime.h>

// BayesianMetaPosterior: scalar loss from two reductions.
//   S_sq  = sum(metamean^2)   over D elements
//   S_lg2 = sum(log2(fishers)) over M*D elements   (scaled by ln2 at the end)
//   loss  = (M-1)*( S_sq/(2*sigma^2) + D*(log(sigma)+0.5*log(2pi)) )
//         + ( -0.5*M*D*log(2pi) + 0.5*ln2*S_lg2 )
// `means` (d_in[1]) is mathematically unused (Mahalanobis term == 0).

#define NB_M 296
#define NB_F 888
#define NB   (NB_M + NB_F)   // 1184 = 148 SMs * 8 CTAs (one wave @ 256 thr, 32 regs)
#define NT   256

__device__ double g_part_sq[NB_M];
__device__ double g_part_log[NB_F];
__device__ unsigned int g_done_count;   // zero-init; self-resets each run

__device__ __forceinline__ double block_reduce(double v) {
    __shared__ double sm[NT / 32];
    #pragma unroll
    for (int off = 16; off > 0; off >>= 1)
        v += __shfl_down_sync(0xFFFFFFFFu, v, off);
    int lane = threadIdx.x & 31, warp = threadIdx.x >> 5;
    if (lane == 0) sm[warp] = v;
    __syncthreads();
    if (warp == 0) {
        v = (lane < NT / 32) ? sm[lane] : 0.0;
        #pragma unroll
        for (int off = 4; off > 0; off >>= 1)
            v += __shfl_down_sync(0xFFFFFFFFu, v, off);
    }
    return v;  // valid in thread 0
}

__global__ __launch_bounds__(NT, 8)
void bmp_kernel(const float* __restrict__ metamean,
                const float* __restrict__ fishers,
                long long D, long long MD, int M,
                float* __restrict__ out, int out_size)
{
    const bool is_fish = (blockIdx.x >= NB_M);
    const float4* __restrict__ base =
        reinterpret_cast<const float4*>(is_fish ? fishers : metamean);
    const long long nElem = is_fish ? MD : D;
    const long long n4    = nElem >> 2;
    const int  bid = is_fish ? (int)blockIdx.x - NB_M : (int)blockIdx.x;
    const int  nb  = is_fish ? NB_F : NB_M;
    const long long tid    = (long long)bid * NT + threadIdx.x;
    const long long stride = (long long)nb * NT;

    float a0 = 0.f, a1 = 0.f, a2 = 0.f, a3 = 0.f;
    const float4* p  = base + tid;
    const float4* p1 = p + stride;
    const float4* p2 = p + 2 * stride;
    const float4* p3 = p + 3 * stride;
    const float4* end  = base + n4;
    long long i = tid;

    if (is_fish) {
        // ---- sum of log2 over fishers (scale by ln2 once at the end) ----
        for (; i + 3 * stride < n4; i += 4 * stride) {
            float4 v0 = __ldcs(p);
            float4 v1 = __ldcs(p1);
            float4 v2 = __ldcs(p2);
            float4 v3 = __ldcs(p3);
            p += 4 * stride; p1 += 4 * stride; p2 += 4 * stride; p3 += 4 * stride;
            a0 += __log2f(v0.x) + __log2f(v0.y) + __log2f(v0.z) + __log2f(v0.w);
            a1 += __log2f(v1.x) + __log2f(v1.y) + __log2f(v1.z) + __log2f(v1.w);
            a2 += __log2f(v2.x) + __log2f(v2.y) + __log2f(v2.z) + __log2f(v2.w);
            a3 += __log2f(v3.x) + __log2f(v3.y) + __log2f(v3.z) + __log2f(v3.w);
        }
        for (; p < end; p += stride) {
            float4 v = __ldcs(p);
            a0 += __log2f(v.x) + __log2f(v.y) + __log2f(v.z) + __log2f(v.w);
        }
        for (long long j = (n4 << 2) + tid; j < nElem; j += stride)
            a0 += __log2f(__ldg(&fishers[j]));
    } else {
        // ---- sum of squares over metamean ----
        for (; i + 3 * stride < n4; i += 4 * stride) {
            float4 v0 = __ldcs(p);
            float4 v1 = __ldcs(p1);
            float4 v2 = __ldcs(p2);
            float4 v3 = __ldcs(p3);
            p += 4 * stride; p1 += 4 * stride; p2 += 4 * stride; p3 += 4 * stride;
            a0 += v0.x * v0.x + v0.y * v0.y + v0.z * v0.z + v0.w * v0.w;
            a1 += v1.x * v1.x + v1.y * v1.y + v1.z * v1.z + v1.w * v1.w;
            a2 += v2.x * v2.x + v2.y * v2.y + v2.z * v2.z + v2.w * v2.w;
            a3 += v3.x * v3.x + v3.y * v3.y + v3.z * v3.z + v3.w * v3.w;
        }
        for (; p < end; p += stride) {
            float4 v = __ldcs(p);
            a0 += v.x * v.x + v.y * v.y + v.z * v.z + v.w * v.w;
        }
        for (long long j = (n4 << 2) + tid; j < nElem; j += stride) {
            float v = __ldg(&metamean[j]);
            a0 += v * v;
        }
    }

    double acc = ((double)a0 + (double)a1) + ((double)a2 + (double)a3);
    acc = block_reduce(acc);

    __shared__ bool s_last;
    if (threadIdx.x == 0) {
        if (is_fish) g_part_log[bid] = acc;
        else         g_part_sq[bid]  = acc;
        __threadfence();
        unsigned int prev = atomicAdd(&g_done_count, 1u);
        s_last = (prev == NB - 1);
    }
    __syncthreads();

    // ---- last block to finish performs the final reduction ----
    if (s_last) {
        double a = 0.0, b = 0.0;
        for (int k = threadIdx.x; k < NB_M; k += NT) a += g_part_sq[k];
        for (int k = threadIdx.x; k < NB_F; k += NT) b += g_part_log[k];
        a = block_reduce(a);
        __syncthreads();           // smem reuse between block_reduce calls
        b = block_reduce(b);
        if (threadIdx.x == 0) {
            const double log2pi = 1.8378770664093453;      // log(2*pi)
            const double logsig = -2.3025850929940456840;  // log(0.1)
            const double inv2s2 = 50.0;                    // 1/(2*0.1^2)
            const double ln2    = 0.6931471805599453;      // log2 -> ln
            double prior_term = (double)(M - 1) *
                (inv2s2 * a + (double)D * (logsig + 0.5 * log2pi));
            double post_term = -0.5 * (double)M * (double)D * log2pi
                               + 0.5 * ln2 * b;
            float loss = (float)(prior_term + post_term);
            for (int k = 0; k < out_size; k++) out[k] = loss;
            g_done_count = 0;      // self-reset for next graph replay
        }
    }
}

extern "C" void kernel_launch(void* const* d_in, const int* in_sizes, int n_in,
                              void* d_out, int out_size)
{
    const float* metamean = (const float*)d_in[0];
    // d_in[1] = means: unused (Mahalanobis term is identically zero)
    const float* fishers  = (const float*)d_in[2];

    const long long D  = (long long)in_sizes[0];
    const long long MD = (long long)in_sizes[2];
    const int M = (int)(MD / D);

    bmp_kernel<<<NB, NT>>>(metamean, fishers, D, MD, M,
                           (float*)d_out, out_size);
}

// round 4
// speedup vs baseline: 1.9920x; 1.0689x over previous
#include <cuda_runtime.h>

// BayesianMetaPosterior: scalar loss from two reductions.
//   S_sq  = sum(metamean^2)    over D elements
//   S_lg2 = sum(log2(fishers)) over M*D elements (scaled by ln2 at the end)
//   loss  = (M-1)*( S_sq/(2*sigma^2) + D*(log(sigma)+0.5*log(2pi)) )
//         + ( -0.5*M*D*log(2pi) + 0.5*ln2*S_lg2 )
// `means` (d_in[1]) is mathematically unused (Mahalanobis term == 0).
//
// Contiguous-slab partitioning per block (DRAM row locality), unroll-8
// front-batched float4 streaming loads (MLP_p1 = 8), float accumulators,
// double only across threads. Last-finished block finalizes.

#define NB_M 185
#define NB_F 555
#define NB   (NB_M + NB_F)   // 740 = 148 SMs * 5 CTAs (one wave @ 256 thr)
#define NT   256

__device__ double g_part_sq[NB_M];
__device__ double g_part_log[NB_F];
__device__ unsigned int g_done_count;   // zero-init; self-resets each run

__device__ __forceinline__ double block_reduce(double v) {
    __shared__ double sm[NT / 32];
    #pragma unroll
    for (int off = 16; off > 0; off >>= 1)
        v += __shfl_down_sync(0xFFFFFFFFu, v, off);
    int lane = threadIdx.x & 31, warp = threadIdx.x >> 5;
    if (lane == 0) sm[warp] = v;
    __syncthreads();
    if (warp == 0) {
        v = (lane < NT / 32) ? sm[lane] : 0.0;
        #pragma unroll
        for (int off = 4; off > 0; off >>= 1)
            v += __shfl_down_sync(0xFFFFFFFFu, v, off);
    }
    return v;  // valid in thread 0
}

__global__ __launch_bounds__(NT, 5)
void bmp_kernel(const float* __restrict__ metamean,
                const float* __restrict__ fishers,
                long long D, long long MD, int M,
                float* __restrict__ out, int out_size)
{
    const bool is_fish = (blockIdx.x >= NB_M);
    const float* __restrict__ srcf = is_fish ? fishers : metamean;
    const float4* __restrict__ base = reinterpret_cast<const float4*>(srcf);
    const long long nElem = is_fish ? MD : D;
    const long long n4    = nElem >> 2;
    const int  bid = is_fish ? (int)blockIdx.x - NB_M : (int)blockIdx.x;
    const int  nb  = is_fish ? NB_F : NB_M;

    // contiguous slab of quads for this block
    const long long q_begin = (long long)bid * n4 / nb;
    const long long q_end   = (long long)(bid + 1) * n4 / nb;

    float a0 = 0.f, a1 = 0.f, a2 = 0.f, a3 = 0.f;
    float a4 = 0.f, a5 = 0.f, a6 = 0.f, a7 = 0.f;

    long long q = q_begin + threadIdx.x;

    if (is_fish) {
        for (; q + 7 * NT < q_end; q += 8 * NT) {
            float4 v0 = __ldcs(base + q);
            float4 v1 = __ldcs(base + q + 1 * NT);
            float4 v2 = __ldcs(base + q + 2 * NT);
            float4 v3 = __ldcs(base + q + 3 * NT);
            float4 v4 = __ldcs(base + q + 4 * NT);
            float4 v5 = __ldcs(base + q + 5 * NT);
            float4 v6 = __ldcs(base + q + 6 * NT);
            float4 v7 = __ldcs(base + q + 7 * NT);
            a0 += __log2f(v0.x) + __log2f(v0.y) + __log2f(v0.z) + __log2f(v0.w);
            a1 += __log2f(v1.x) + __log2f(v1.y) + __log2f(v1.z) + __log2f(v1.w);
            a2 += __log2f(v2.x) + __log2f(v2.y) + __log2f(v2.z) + __log2f(v2.w);
            a3 += __log2f(v3.x) + __log2f(v3.y) + __log2f(v3.z) + __log2f(v3.w);
            a4 += __log2f(v4.x) + __log2f(v4.y) + __log2f(v4.z) + __log2f(v4.w);
            a5 += __log2f(v5.x) + __log2f(v5.y) + __log2f(v5.z) + __log2f(v5.w);
            a6 += __log2f(v6.x) + __log2f(v6.y) + __log2f(v6.z) + __log2f(v6.w);
            a7 += __log2f(v7.x) + __log2f(v7.y) + __log2f(v7.z) + __log2f(v7.w);
        }
        for (; q < q_end; q += NT) {
            float4 v = __ldcs(base + q);
            a0 += __log2f(v.x) + __log2f(v.y) + __log2f(v.z) + __log2f(v.w);
        }
        // scalar tail of the whole region (only last block)
        if (bid == nb - 1) {
            for (long long j = (n4 << 2) + threadIdx.x; j < nElem; j += NT)
                a0 += __log2f(__ldg(&srcf[j]));
        }
    } else {
        for (; q + 7 * NT < q_end; q += 8 * NT) {
            float4 v0 = __ldcs(base + q);
            float4 v1 = __ldcs(base + q + 1 * NT);
            float4 v2 = __ldcs(base + q + 2 * NT);
            float4 v3 = __ldcs(base + q + 3 * NT);
            float4 v4 = __ldcs(base + q + 4 * NT);
            float4 v5 = __ldcs(base + q + 5 * NT);
            float4 v6 = __ldcs(base + q + 6 * NT);
            float4 v7 = __ldcs(base + q + 7 * NT);
            a0 += v0.x * v0.x + v0.y * v0.y + v0.z * v0.z + v0.w * v0.w;
            a1 += v1.x * v1.x + v1.y * v1.y + v1.z * v1.z + v1.w * v1.w;
            a2 += v2.x * v2.x + v2.y * v2.y + v2.z * v2.z + v2.w * v2.w;
            a3 += v3.x * v3.x + v3.y * v3.y + v3.z * v3.z + v3.w * v3.w;
            a4 += v4.x * v4.x + v4.y * v4.y + v4.z * v4.z + v4.w * v4.w;
            a5 += v5.x * v5.x + v5.y * v5.y + v5.z * v5.z + v5.w * v5.w;
            a6 += v6.x * v6.x + v6.y * v6.y + v6.z * v6.z + v6.w * v6.w;
            a7 += v7.x * v7.x + v7.y * v7.y + v7.z * v7.z + v7.w * v7.w;
        }
        for (; q < q_end; q += NT) {
            float4 v = __ldcs(base + q);
            a0 += v.x * v.x + v.y * v.y + v.z * v.z + v.w * v.w;
        }
        if (bid == nb - 1) {
            for (long long j = (n4 << 2) + threadIdx.x; j < nElem; j += NT) {
                float v = __ldg(&srcf[j]);
                a0 += v * v;
            }
        }
    }

    double acc = (((double)a0 + (double)a1) + ((double)a2 + (double)a3))
               + (((double)a4 + (double)a5) + ((double)a6 + (double)a7));
    acc = block_reduce(acc);

    __shared__ bool s_last;
    if (threadIdx.x == 0) {
        if (is_fish) g_part_log[bid] = acc;
        else         g_part_sq[bid]  = acc;
        __threadfence();
        unsigned int prev = atomicAdd(&g_done_count, 1u);
        s_last = (prev == NB - 1);
    }
    __syncthreads();

    // ---- last block to finish performs the final reduction ----
    if (s_last) {
        double a = 0.0, b = 0.0;
        for (int k = threadIdx.x; k < NB_M; k += NT) a += g_part_sq[k];
        for (int k = threadIdx.x; k < NB_F; k += NT) b += g_part_log[k];
        a = block_reduce(a);
        __syncthreads();           // smem reuse between block_reduce calls
        b = block_reduce(b);
        if (threadIdx.x == 0) {
            const double log2pi = 1.8378770664093453;      // log(2*pi)
            const double logsig = -2.3025850929940456840;  // log(0.1)
            const double inv2s2 = 50.0;                    // 1/(2*0.1^2)
            const double ln2    = 0.6931471805599453;      // log2 -> ln
            double prior_term = (double)(M - 1) *
                (inv2s2 * a + (double)D * (logsig + 0.5 * log2pi));
            double post_term = -0.5 * (double)M * (double)D * log2pi
                               + 0.5 * ln2 * b;
            float loss = (float)(prior_term + post_term);
            for (int k = 0; k < out_size; k++) out[k] = loss;
            g_done_count = 0;      // self-reset for next graph replay
        }
    }
}

extern "C" void kernel_launch(void* const* d_in, const int* in_sizes, int n_in,
                              void* d_out, int out_size)
{
    const float* metamean = (const float*)d_in[0];
    // d_in[1] = means: unused (Mahalanobis term is identically zero)
    const float* fishers  = (const float*)d_in[2];

    const long long D  = (long long)in_sizes[0];
    const long long MD = (long long)in_sizes[2];
    const int M = (int)(MD / D);

    bmp_kernel<<<NB, NT>>>(metamean, fishers, D, MD, M,
                           (float*)d_out, out_size);
}